// round 2
// baseline (speedup 1.0000x reference)
#include <cuda_runtime.h>
#include <math.h>

#define D_MODEL 1024
#define N_HEADS 16
#define D_HEAD  64
#define K_WIN   8
#define DIL     2
#define BATCH   2
#define SEQ     2048
#define M_TOTAL (BATCH * SEQ)          // 4096 tokens
#define QKV_COLS (3 * D_MODEL)         // 3072

// Scratch (no cudaMalloc allowed): qkv projection + attention output.
// Referenced directly from device code — no host-side symbol lookup needed.
__device__ float g_qkv[(size_t)M_TOTAL * QKV_COLS];   // 50.3 MB
__device__ float g_att[(size_t)M_TOTAL * D_MODEL];    // 16.8 MB

// ---------------------------------------------------------------------------
// SGEMM: C[M,N] = A[M,K] @ W[N,K]^T + bias[N]
// 128x128 block tile, BK=16, 256 threads, 8x8 per thread.
// ---------------------------------------------------------------------------
#define BM 128
#define BN 128
#define BK 16

__global__ __launch_bounds__(256, 2)
void sgemm_bias_kernel(const float* __restrict__ A,
                       const float* __restrict__ W,
                       const float* __restrict__ bias,
                       float* __restrict__ C,
                       int M, int N, int K)
{
    __shared__ float As[BK][BM + 4];
    __shared__ float Bs[BK][BN + 4];

    const int tid = threadIdx.x;
    const int tx  = tid & 15;          // 0..15 -> N direction
    const int ty  = tid >> 4;          // 0..15 -> M direction
    const int bm  = blockIdx.y * BM;
    const int bn  = blockIdx.x * BN;

    const float* Ab = A + (size_t)bm * K;
    const float* Wb = W + (size_t)bn * K;

    float acc[8][8];
#pragma unroll
    for (int i = 0; i < 8; i++)
#pragma unroll
        for (int j = 0; j < 8; j++)
            acc[i][j] = 0.f;

    for (int k0 = 0; k0 < K; k0 += BK) {
        // Load 128x16 tiles of A and W, transposed into smem.
        // 512 float4 per tile, 256 threads -> 2 each.
#pragma unroll
        for (int l = 0; l < 2; l++) {
            int idx = tid + l * 256;
            int row = idx >> 2;        // 0..127
            int c4  = (idx & 3) * 4;   // 0,4,8,12
            float4 va = *(const float4*)(Ab + (size_t)row * K + k0 + c4);
            As[c4 + 0][row] = va.x;
            As[c4 + 1][row] = va.y;
            As[c4 + 2][row] = va.z;
            As[c4 + 3][row] = va.w;
            float4 vb = *(const float4*)(Wb + (size_t)row * K + k0 + c4);
            Bs[c4 + 0][row] = vb.x;
            Bs[c4 + 1][row] = vb.y;
            Bs[c4 + 2][row] = vb.z;
            Bs[c4 + 3][row] = vb.w;
        }
        __syncthreads();

#pragma unroll
        for (int kk = 0; kk < BK; kk++) {
            float4 a0 = *(const float4*)&As[kk][ty * 8];
            float4 a1 = *(const float4*)&As[kk][ty * 8 + 4];
            float4 b0 = *(const float4*)&Bs[kk][tx * 8];
            float4 b1 = *(const float4*)&Bs[kk][tx * 8 + 4];
            float a[8] = {a0.x, a0.y, a0.z, a0.w, a1.x, a1.y, a1.z, a1.w};
            float b[8] = {b0.x, b0.y, b0.z, b0.w, b1.x, b1.y, b1.z, b1.w};
#pragma unroll
            for (int i = 0; i < 8; i++)
#pragma unroll
                for (int j = 0; j < 8; j++)
                    acc[i][j] = fmaf(a[i], b[j], acc[i][j]);
        }
        __syncthreads();
    }

    // Epilogue: add bias, store.
    float4 bia0 = *(const float4*)(bias + bn + tx * 8);
    float4 bia1 = *(const float4*)(bias + bn + tx * 8 + 4);
    float bb[8] = {bia0.x, bia0.y, bia0.z, bia0.w, bia1.x, bia1.y, bia1.z, bia1.w};

#pragma unroll
    for (int i = 0; i < 8; i++) {
        int gm = bm + ty * 8 + i;
        float* Crow = C + (size_t)gm * N + bn + tx * 8;
        float4 o0 = make_float4(acc[i][0] + bb[0], acc[i][1] + bb[1],
                                acc[i][2] + bb[2], acc[i][3] + bb[3]);
        float4 o1 = make_float4(acc[i][4] + bb[4], acc[i][5] + bb[5],
                                acc[i][6] + bb[6], acc[i][7] + bb[7]);
        *(float4*)(Crow)     = o0;
        *(float4*)(Crow + 4) = o1;
    }
}

// GEMM wrappers binding scratch globals directly (avoids host symbol lookup).
__global__ void __launch_bounds__(256, 2)
sgemm_qkv_entry(const float* __restrict__ A,
                const float* __restrict__ W,
                const float* __restrict__ bias);

// ---------------------------------------------------------------------------
// QK-norm: L2-normalize each 64-element head vector of q and k (in place).
// One warp per segment: M_TOTAL tokens * 32 segments (16 q-heads + 16 k-heads)
// ---------------------------------------------------------------------------
__global__ void qknorm_kernel()
{
    int gw   = (blockIdx.x * blockDim.x + threadIdx.x) >> 5;
    int lane = threadIdx.x & 31;
    if (gw >= M_TOTAL * 32) return;
    int row = gw >> 5;         // token
    int seg = gw & 31;         // 0..15 q heads, 16..31 k heads
    size_t off = (size_t)row * QKV_COLS +
                 (seg < 16 ? seg * 64 : D_MODEL + (seg - 16) * 64);
    float* p = g_qkv + off;
    float2 v = *(float2*)(p + lane * 2);
    float ss = v.x * v.x + v.y * v.y;
#pragma unroll
    for (int o = 16; o; o >>= 1) ss += __shfl_xor_sync(0xFFFFFFFFu, ss, o);
    float inv = 1.0f / (sqrtf(ss) + 1e-6f);
    v.x *= inv; v.y *= inv;
    *(float2*)(p + lane * 2) = v;
}

// ---------------------------------------------------------------------------
// Dilated attention: one warp per (token, head).
// Window: j = i + 2*(t-8), t in [0,17), clipped to [0,SEQ). scale = 1.0
// ---------------------------------------------------------------------------
__global__ void attend_kernel()
{
    int gw   = (blockIdx.x * blockDim.x + threadIdx.x) >> 5;
    int lane = threadIdx.x & 31;
    if (gw >= M_TOTAL * N_HEADS) return;
    int r = gw >> 4;           // token index 0..4095
    int h = gw & 15;
    int b = r / SEQ;
    int i = r % SEQ;

    const float* qp = g_qkv + (size_t)r * QKV_COLS + h * 64;
    const float* kb = g_qkv + (size_t)(b * SEQ) * QKV_COLS + D_MODEL + h * 64;
    const float* vb = g_qkv + (size_t)(b * SEQ) * QKV_COLS + 2 * D_MODEL + h * 64;

    float2 q = *(const float2*)(qp + lane * 2);

    float sc[17];
#pragma unroll
    for (int t = 0; t < 17; t++) {
        int j = i + 2 * (t - K_WIN);
        float s = -INFINITY;
        if (j >= 0 && j < SEQ) {
            float2 k = *(const float2*)(kb + (size_t)j * QKV_COLS + lane * 2);
            float d = q.x * k.x + q.y * k.y;
#pragma unroll
            for (int o = 16; o; o >>= 1) d += __shfl_xor_sync(0xFFFFFFFFu, d, o);
            s = d;
        }
        sc[t] = s;
    }

    float mx = -INFINITY;
#pragma unroll
    for (int t = 0; t < 17; t++) mx = fmaxf(mx, sc[t]);
    float den = 0.f;
#pragma unroll
    for (int t = 0; t < 17; t++) {
        float e = (sc[t] == -INFINITY) ? 0.f : __expf(sc[t] - mx);
        sc[t] = e;
        den += e;
    }
    float inv = 1.0f / den;   // den >= 1: j=i always valid -> exp(0) term present

    float2 acc = make_float2(0.f, 0.f);
#pragma unroll
    for (int t = 0; t < 17; t++) {
        int j = i + 2 * (t - K_WIN);
        if (j >= 0 && j < SEQ) {
            float2 v = *(const float2*)(vb + (size_t)j * QKV_COLS + lane * 2);
            float p = sc[t] * inv;
            acc.x = fmaf(p, v.x, acc.x);
            acc.y = fmaf(p, v.y, acc.y);
        }
    }
    *(float2*)(g_att + (size_t)r * D_MODEL + h * 64 + lane * 2) = acc;
}

// ---------------------------------------------------------------------------
// Thin __global__ wrappers that bind the device-global scratch buffers as
// GEMM operands without any host-side address resolution.
// ---------------------------------------------------------------------------
__global__ __launch_bounds__(256, 2)
void sgemm_x_to_qkv(const float* __restrict__ x,
                    const float* __restrict__ qkv_w,
                    const float* __restrict__ qkv_b);
__global__ __launch_bounds__(256, 2)
void sgemm_att_to_out(const float* __restrict__ out_w,
                      const float* __restrict__ out_b,
                      float* __restrict__ out);

// Implement the wrappers by duplicating the sgemm body via a device function.
__device__ __forceinline__
void sgemm_body(const float* __restrict__ A,
                const float* __restrict__ W,
                const float* __restrict__ bias,
                float* __restrict__ C,
                int N, int K)
{
    __shared__ float As[BK][BM + 4];
    __shared__ float Bs[BK][BN + 4];

    const int tid = threadIdx.x;
    const int tx  = tid & 15;
    const int ty  = tid >> 4;
    const int bm  = blockIdx.y * BM;
    const int bn  = blockIdx.x * BN;

    const float* Ab = A + (size_t)bm * K;
    const float* Wb = W + (size_t)bn * K;

    float acc[8][8];
#pragma unroll
    for (int i = 0; i < 8; i++)
#pragma unroll
        for (int j = 0; j < 8; j++)
            acc[i][j] = 0.f;

    for (int k0 = 0; k0 < K; k0 += BK) {
#pragma unroll
        for (int l = 0; l < 2; l++) {
            int idx = tid + l * 256;
            int row = idx >> 2;
            int c4  = (idx & 3) * 4;
            float4 va = *(const float4*)(Ab + (size_t)row * K + k0 + c4);
            As[c4 + 0][row] = va.x;
            As[c4 + 1][row] = va.y;
            As[c4 + 2][row] = va.z;
            As[c4 + 3][row] = va.w;
            float4 vb = *(const float4*)(Wb + (size_t)row * K + k0 + c4);
            Bs[c4 + 0][row] = vb.x;
            Bs[c4 + 1][row] = vb.y;
            Bs[c4 + 2][row] = vb.z;
            Bs[c4 + 3][row] = vb.w;
        }
        __syncthreads();

#pragma unroll
        for (int kk = 0; kk < BK; kk++) {
            float4 a0 = *(const float4*)&As[kk][ty * 8];
            float4 a1 = *(const float4*)&As[kk][ty * 8 + 4];
            float4 b0 = *(const float4*)&Bs[kk][tx * 8];
            float4 b1 = *(const float4*)&Bs[kk][tx * 8 + 4];
            float a[8] = {a0.x, a0.y, a0.z, a0.w, a1.x, a1.y, a1.z, a1.w};
            float b[8] = {b0.x, b0.y, b0.z, b0.w, b1.x, b1.y, b1.z, b1.w};
#pragma unroll
            for (int i = 0; i < 8; i++)
#pragma unroll
                for (int j = 0; j < 8; j++)
                    acc[i][j] = fmaf(a[i], b[j], acc[i][j]);
        }
        __syncthreads();
    }

    float4 bia0 = *(const float4*)(bias + bn + tx * 8);
    float4 bia1 = *(const float4*)(bias + bn + tx * 8 + 4);
    float bb[8] = {bia0.x, bia0.y, bia0.z, bia0.w, bia1.x, bia1.y, bia1.z, bia1.w};

#pragma unroll
    for (int i = 0; i < 8; i++) {
        int gm = bm + ty * 8 + i;
        float* Crow = C + (size_t)gm * N + bn + tx * 8;
        float4 o0 = make_float4(acc[i][0] + bb[0], acc[i][1] + bb[1],
                                acc[i][2] + bb[2], acc[i][3] + bb[3]);
        float4 o1 = make_float4(acc[i][4] + bb[4], acc[i][5] + bb[5],
                                acc[i][6] + bb[6], acc[i][7] + bb[7]);
        *(float4*)(Crow)     = o0;
        *(float4*)(Crow + 4) = o1;
    }
}

__global__ __launch_bounds__(256, 2)
void sgemm_x_to_qkv(const float* __restrict__ x,
                    const float* __restrict__ qkv_w,
                    const float* __restrict__ qkv_b)
{
    sgemm_body(x, qkv_w, qkv_b, g_qkv, QKV_COLS, D_MODEL);
}

__global__ __launch_bounds__(256, 2)
void sgemm_att_to_out(const float* __restrict__ out_w,
                      const float* __restrict__ out_b,
                      float* __restrict__ out)
{
    sgemm_body(g_att, out_w, out_b, out, D_MODEL, D_MODEL);
}

// ---------------------------------------------------------------------------
// Launch: pure kernel launches, nothing else (graph-capture safe).
// ---------------------------------------------------------------------------
extern "C" void kernel_launch(void* const* d_in, const int* in_sizes, int n_in,
                              void* d_out, int out_size)
{
    const float* x     = (const float*)d_in[0];
    const float* qkv_w = (const float*)d_in[1];
    const float* qkv_b = (const float*)d_in[2];
    const float* out_w = (const float*)d_in[3];
    const float* out_b = (const float*)d_in[4];
    float* out = (float*)d_out;

    // 1) QKV projection: (4096,1024) @ (3072,1024)^T -> g_qkv (4096,3072)
    {
        dim3 grid(QKV_COLS / BN, M_TOTAL / BM);
        sgemm_x_to_qkv<<<grid, 256>>>(x, qkv_w, qkv_b);
    }

    // 2) QK L2-normalization (in place on g_qkv)
    qknorm_kernel<<<(M_TOTAL * 32) / 8, 256>>>();

    // 3) Dilated windowed attention -> g_att
    attend_kernel<<<(M_TOTAL * N_HEADS) / 8, 256>>>();

    // 4) Output projection: g_att (4096,1024) @ (1024,1024)^T -> out
    {
        dim3 grid(D_MODEL / BN, M_TOTAL / BM);
        sgemm_att_to_out<<<grid, 256>>>(out_w, out_b, out);
    }
}